// round 1
// baseline (speedup 1.0000x reference)
#include <cuda_runtime.h>
#include <math.h>

#define S      2048
#define ND     128
#define NH     24      // 3*H heads total
#define DK     32      // channels per head
#define DV     128     // value dim per head
#define KQ_OUT 512     // H*C*2
#define VOUT   3072    // ND*H*3

#define TI 32          // i rows per attention block
#define TJ 64          // j rows per tile

// scratch (device globals — no allocation allowed)
__device__ float g_K[S * NH * DK];   // K[s][h][c]
__device__ float g_Q[S * NH * DK];   // Q[s][h][c]
__device__ float g_V[S * VOUT];      // V[s][h*128 + d]

// ---------------------------------------------------------------------------
// zero output (out is poisoned; attention uses atomicAdd)
// ---------------------------------------------------------------------------
__global__ void zero_kernel(float* out) {
    int i = blockIdx.x * blockDim.x + threadIdx.x;
    if (i < S * ND) out[i] = 0.f;
}

// ---------------------------------------------------------------------------
// P1: values GEMM  g_V[s][o] = nodes[s] . w_values[o] + b_values[o]
// grid (VOUT/64, S/16), block 256. Each thread: 1 s-row x 4 o-cols (stride 16).
// ---------------------------------------------------------------------------
__global__ void val_kernel(const float* __restrict__ nodes,
                           const float* __restrict__ wV,
                           const float* __restrict__ bV) {
    __shared__ float sA[16 * 129];
    __shared__ float sW[64 * 129];
    int t  = threadIdx.x;
    int o0 = blockIdx.x * 64;
    int s0 = blockIdx.y * 16;

    for (int e = t; e < 16 * 128; e += 256) {
        int r = e >> 7, k = e & 127;
        sA[r * 129 + k] = nodes[(s0 + r) * ND + k];
    }
    for (int e = t; e < 64 * 128; e += 256) {
        int r = e >> 7, k = e & 127;
        sW[r * 129 + k] = wV[(o0 + r) * ND + k];
    }
    __syncthreads();

    int tx = t & 15, ty = t >> 4;
    float a0 = bV[o0 + tx];
    float a1 = bV[o0 + tx + 16];
    float a2 = bV[o0 + tx + 32];
    float a3 = bV[o0 + tx + 48];
    const float* ar = &sA[ty * 129];
    const float* w0 = &sW[(tx     ) * 129];
    const float* w1 = &sW[(tx + 16) * 129];
    const float* w2 = &sW[(tx + 32) * 129];
    const float* w3 = &sW[(tx + 48) * 129];
#pragma unroll 8
    for (int k = 0; k < 128; k++) {
        float a = ar[k];
        a0 += a * w0[k];
        a1 += a * w1[k];
        a2 += a * w2[k];
        a3 += a * w3[k];
    }
    int s = s0 + ty;
    g_V[s * VOUT + o0 + tx     ] = a0;
    g_V[s * VOUT + o0 + tx + 16] = a1;
    g_V[s * VOUT + o0 + tx + 32] = a2;
    g_V[s * VOUT + o0 + tx + 48] = a3;
}

// ---------------------------------------------------------------------------
// P2: K/Q projections from nodes, pos features (cos/sin), rot — scattered into
// the concatenated head layout: heads 0-7 nodes, 8-15 pos, 16-23 rot.
// grid (KQ_OUT/16, S/16), block 256.
// ---------------------------------------------------------------------------
__global__ void kq_kernel(const float* __restrict__ nodes,
                          const float* __restrict__ pos,
                          const float* __restrict__ rot,
                          const float* __restrict__ wN, const float* __restrict__ bNb,
                          const float* __restrict__ wP, const float* __restrict__ bPb,
                          const float* __restrict__ wR) {
    __shared__ float sN[16 * 129];
    __shared__ float sW[16 * 129];
    __shared__ float sPF[16 * 6];
    __shared__ float sR[16 * 4];
    int t  = threadIdx.x;
    int o0 = blockIdx.x * 16;
    int s0 = blockIdx.y * 16;

    for (int e = t; e < 16 * 128; e += 256) {
        int r = e >> 7, k = e & 127;
        sN[r * 129 + k] = nodes[(s0 + r) * ND + k];
        sW[r * 129 + k] = wN[(o0 + r) * ND + k];
    }
    if (t < 16) {
        int s = s0 + t;
#pragma unroll
        for (int a = 0; a < 3; a++) {
            float v = 6.283185307179586f * pos[s * 3 + a];
            float sv, cv;
            sincosf(v, &sv, &cv);
            sPF[t * 6 + a]     = cv;
            sPF[t * 6 + 3 + a] = sv;
        }
#pragma unroll
        for (int a = 0; a < 4; a++) sR[t * 4 + a] = rot[s * 4 + a];
    }
    __syncthreads();

    int tx = t & 15, ty = t >> 4;
    int o = o0 + tx;

    float aN = bNb[o];
    const float* nr = &sN[ty * 129];
    const float* wr = &sW[tx * 129];
#pragma unroll 8
    for (int k = 0; k < 128; k++) aN += nr[k] * wr[k];

    float aP = bPb[o];
#pragma unroll
    for (int k = 0; k < 6; k++) aP += sPF[ty * 6 + k] * wP[o * 6 + k];

    float aR = 0.f;
#pragma unroll
    for (int k = 0; k < 4; k++) aR += sR[ty * 4 + k] * wR[o * 4 + k];

    int hl = o >> 6, c = o & 63;
    int s = s0 + ty;
    float* dst = (c < 32) ? g_K : g_Q;
    int cc = c & 31;
    dst[(s * NH + hl     ) * DK + cc] = aN;
    dst[(s * NH + 8  + hl) * DK + cc] = aP;
    dst[(s * NH + 16 + hl) * DK + cc] = aR;
}

// ---------------------------------------------------------------------------
// Attention: one block per (i-tile of 32, head). Online softmax over j tiles
// of 64. logits[i,j] = k_i . q_j (squared for rot heads). out += att @ V_h.
// 256 threads:
//   logits phase: thread = (ii = t>>3 row, jb = t&7 j-slice), 8 j each
//   PV phase:     thread = (d0 = (t&63)*2 two dims, qv = t>>6 row quarter), 8 rows
// ---------------------------------------------------------------------------
#define SMEM_FLOATS (TI*33 + TJ*33 + TJ*DV + TI*72 + 3*TI)

__global__ void attn_kernel(float* __restrict__ out) {
    extern __shared__ float sm[];
    float* sK  = sm;                  // TI x 33 (padded)
    float* sQ  = sK + TI * 33;        // TJ x 33
    float* sV  = sQ + TJ * 33;        // TJ x 128
    float* sP  = sV + TJ * DV;        // TI x 72 (padded)
    float* sM  = sP + TI * 72;        // TI
    float* sL  = sM + TI;             // TI
    float* sSc = sL + TI;             // TI

    int t  = threadIdx.x;
    int i0 = blockIdx.x * TI;
    int h  = blockIdx.y;
    bool isRot = (h >= 16);

    for (int e = t; e < TI * DK; e += 256) {
        int r = e >> 5, c = e & 31;
        sK[r * 33 + c] = g_K[((i0 + r) * NH + h) * DK + c];
    }
    if (t < TI) { sM[t] = -INFINITY; sL[t] = 0.f; }

    float acc[16];
#pragma unroll
    for (int u = 0; u < 16; u++) acc[u] = 0.f;

    int ii = t >> 3, jb = t & 7;
    int d0 = (t & 63) * 2, qv = t >> 6;

    __syncthreads();

    for (int jt = 0; jt < S / TJ; jt++) {
        int j0 = jt * TJ;
        for (int e = t; e < TJ * DK; e += 256) {
            int r = e >> 5, c = e & 31;
            sQ[r * 33 + c] = g_Q[((j0 + r) * NH + h) * DK + c];
        }
        for (int e = t; e < TJ * DV; e += 256) {
            int r = e >> 7, dd = e & 127;
            sV[r * DV + dd] = g_V[(j0 + r) * VOUT + h * DV + dd];
        }
        __syncthreads();

        // ---- logits + online softmax state ----
        float lv[8];
        float lmax = -INFINITY;
        const float* kr = &sK[ii * 33];
#pragma unroll
        for (int kk = 0; kk < 8; kk++) {
            const float* qr = &sQ[(jb + 8 * kk) * 33];
            float ds = 0.f;
#pragma unroll
            for (int c = 0; c < 32; c++) ds += kr[c] * qr[c];
            if (isRot) ds = ds * ds;
            lv[kk] = ds;
            lmax = fmaxf(lmax, ds);
        }
#pragma unroll
        for (int off = 4; off; off >>= 1)
            lmax = fmaxf(lmax, __shfl_xor_sync(0xffffffffu, lmax, off));

        float mOld = sM[ii];
        float mNew = fmaxf(mOld, lmax);
        float psum = 0.f;
#pragma unroll
        for (int kk = 0; kk < 8; kk++) {
            float p = __expf(lv[kk] - mNew);
            sP[ii * 72 + jb + 8 * kk] = p;
            psum += p;
        }
#pragma unroll
        for (int off = 4; off; off >>= 1)
            psum += __shfl_xor_sync(0xffffffffu, psum, off);

        float scale = __expf(mOld - mNew);
        if (jb == 0) {
            sM[ii]  = mNew;
            sSc[ii] = scale;
            sL[ii]  = sL[ii] * scale + psum;
        }
        __syncthreads();

        // ---- PV accumulate ----
#pragma unroll
        for (int rr = 0; rr < 8; rr++) {
            float sc = sSc[qv * 8 + rr];
            acc[2 * rr]     *= sc;
            acc[2 * rr + 1] *= sc;
        }
#pragma unroll 4
        for (int jj = 0; jj < TJ; jj++) {
            float2 v = *reinterpret_cast<const float2*>(&sV[jj * DV + d0]);
#pragma unroll
            for (int rr = 0; rr < 8; rr++) {
                float p = sP[(qv * 8 + rr) * 72 + jj];
                acc[2 * rr]     += p * v.x;
                acc[2 * rr + 1] += p * v.y;
            }
        }
        __syncthreads();
    }

    // ---- head-sum into output ----
#pragma unroll
    for (int rr = 0; rr < 8; rr++) {
        int r = qv * 8 + rr;
        float inv = 1.0f / sL[r];
        atomicAdd(&out[(i0 + r) * DV + d0],     acc[2 * rr]     * inv);
        atomicAdd(&out[(i0 + r) * DV + d0 + 1], acc[2 * rr + 1] * inv);
    }
}

// ---------------------------------------------------------------------------
extern "C" void kernel_launch(void* const* d_in, const int* in_sizes, int n_in,
                              void* d_out, int out_size) {
    const float* nodes = (const float*)d_in[0];
    const float* pos   = (const float*)d_in[1];
    const float* rot   = (const float*)d_in[2];
    const float* wN    = (const float*)d_in[3];
    const float* bN    = (const float*)d_in[4];
    const float* wP    = (const float*)d_in[5];
    const float* bP    = (const float*)d_in[6];
    const float* wR    = (const float*)d_in[7];
    const float* wV    = (const float*)d_in[8];
    const float* bV    = (const float*)d_in[9];
    float* out = (float*)d_out;

    zero_kernel<<<(S * ND + 255) / 256, 256>>>(out);
    val_kernel<<<dim3(VOUT / 64, S / 16), 256>>>(nodes, wV, bV);
    kq_kernel<<<dim3(KQ_OUT / 16, S / 16), 256>>>(nodes, pos, rot, wN, bN, wP, bP, wR);

    size_t smem = SMEM_FLOATS * sizeof(float);
    cudaFuncSetAttribute(attn_kernel, cudaFuncAttributeMaxDynamicSharedMemorySize, (int)smem);
    attn_kernel<<<dim3(S / TI, NH), 256, smem>>>(out);
}

// round 7
// speedup vs baseline: 2.7513x; 2.7513x over previous
#include <cuda_runtime.h>
#include <cuda_bf16.h>
#include <stdint.h>
#include <math.h>

#define S   2048
#define ND  128
#define NH  24
#define DK  32
#define DV  128
#define L2E 1.4426950408889634f

// hi/lo bf16 split operands (device globals — no allocation allowed)
__device__ __nv_bfloat16 g_Kh[NH * S * DK], g_Kl[NH * S * DK];   // [h][s][c]
__device__ __nv_bfloat16 g_Qh[NH * S * DK], g_Ql[NH * S * DK];   // [h][s][c]
__device__ __nv_bfloat16 g_Vh[NH * S * DV], g_Vl[NH * S * DV];   // [h][s][d]

// ---------------------------------------------------------------------------
static __device__ __forceinline__ uint32_t smem_u32(const void* p) {
    uint32_t a;
    asm("{ .reg .u64 t; cvta.to.shared.u64 t, %1; cvt.u32.u64 %0, t; }" : "=r"(a) : "l"(p));
    return a;
}
static __device__ __forceinline__ void ldsm4(uint32_t* r, uint32_t a) {
    asm volatile("ldmatrix.sync.aligned.m8n8.x4.shared.b16 {%0,%1,%2,%3}, [%4];"
                 : "=r"(r[0]), "=r"(r[1]), "=r"(r[2]), "=r"(r[3]) : "r"(a));
}
static __device__ __forceinline__ void ldsm4t(uint32_t* r, uint32_t a) {
    asm volatile("ldmatrix.sync.aligned.m8n8.x4.trans.shared.b16 {%0,%1,%2,%3}, [%4];"
                 : "=r"(r[0]), "=r"(r[1]), "=r"(r[2]), "=r"(r[3]) : "r"(a));
}
static __device__ __forceinline__ void mma16816(float* d, const uint32_t* a,
                                                uint32_t b0, uint32_t b1) {
    asm volatile("mma.sync.aligned.m16n8k16.row.col.f32.bf16.bf16.f32 "
                 "{%0,%1,%2,%3}, {%4,%5,%6,%7}, {%8,%9}, {%0,%1,%2,%3};"
                 : "+f"(d[0]), "+f"(d[1]), "+f"(d[2]), "+f"(d[3])
                 : "r"(a[0]), "r"(a[1]), "r"(a[2]), "r"(a[3]), "r"(b0), "r"(b1));
}

// fast exp2 on the FMA pipe (no MUFU). |rel err| ~2e-6.
static __device__ __forceinline__ float fexp2(float y) {
    y = fmaxf(y, -120.0f);
    float t = y + 12582912.0f;
    int   n = __float_as_int(t) << 23;
    float f = y - (t - 12582912.0f);
    float p =              1.3333558e-3f;
    p = fmaf(p, f, 9.6181291e-3f);
    p = fmaf(p, f, 5.5504109e-2f);
    p = fmaf(p, f, 2.4022651e-1f);
    p = fmaf(p, f, 6.9314718e-1f);
    p = fmaf(p, f, 1.0f);
    return __int_as_float(__float_as_int(p) + n);
}

static __device__ __forceinline__ void split_store(__nv_bfloat16* ph, __nv_bfloat16* pl,
                                                   int idx, float x) {
    __nv_bfloat16 hv = __float2bfloat16_rn(x);
    ph[idx] = hv;
    pl[idx] = __float2bfloat16_rn(x - __bfloat162float(hv));
}
static __device__ __forceinline__ uint32_t pack2(float a, float b) {
    __nv_bfloat162 v = __floats2bfloat162_rn(a, b);   // a -> low, b -> high
    return *reinterpret_cast<uint32_t*>(&v);
}

// ---------------------------------------------------------------------------
__global__ void zero_kernel(float* out) {
    int i = blockIdx.x * blockDim.x + threadIdx.x;
    if (i < S * ND) out[i] = 0.f;
}

// ---------------------------------------------------------------------------
// P1: values GEMM -> split bf16 g_Vh/g_Vl [h][s][d]
// ---------------------------------------------------------------------------
__global__ void val_kernel(const float* __restrict__ nodes,
                           const float* __restrict__ wV,
                           const float* __restrict__ bV) {
    __shared__ float sA[16 * 129];
    __shared__ float sW[64 * 129];
    int t  = threadIdx.x;
    int o0 = blockIdx.x * 64;
    int s0 = blockIdx.y * 16;

    for (int e = t; e < 16 * 128; e += 256) {
        int r = e >> 7, k = e & 127;
        sA[r * 129 + k] = nodes[(s0 + r) * ND + k];
    }
    for (int e = t; e < 64 * 128; e += 256) {
        int r = e >> 7, k = e & 127;
        sW[r * 129 + k] = wV[(o0 + r) * ND + k];
    }
    __syncthreads();

    int tx = t & 15, ty = t >> 4;
    float a0 = bV[o0 + tx];
    float a1 = bV[o0 + tx + 16];
    float a2 = bV[o0 + tx + 32];
    float a3 = bV[o0 + tx + 48];
    const float* ar = &sA[ty * 129];
    const float* w0 = &sW[(tx     ) * 129];
    const float* w1 = &sW[(tx + 16) * 129];
    const float* w2 = &sW[(tx + 32) * 129];
    const float* w3 = &sW[(tx + 48) * 129];
#pragma unroll 8
    for (int k = 0; k < 128; k++) {
        float a = ar[k];
        a0 += a * w0[k];
        a1 += a * w1[k];
        a2 += a * w2[k];
        a3 += a * w3[k];
    }
    int s = s0 + ty;
#pragma unroll
    for (int u = 0; u < 4; u++) {
        float v = (u == 0) ? a0 : (u == 1) ? a1 : (u == 2) ? a2 : a3;
        int o = o0 + tx + u * 16;
        int hh = o >> 7, d = o & 127;
        split_store(g_Vh, g_Vl, (hh * S + s) * DV + d, v);
    }
}

// ---------------------------------------------------------------------------
// P2: K/Q projections -> split bf16 g_K*/g_Q* [h][s][c]
// ---------------------------------------------------------------------------
__global__ void kq_kernel(const float* __restrict__ nodes,
                          const float* __restrict__ pos,
                          const float* __restrict__ rotv,
                          const float* __restrict__ wN, const float* __restrict__ bNb,
                          const float* __restrict__ wP, const float* __restrict__ bPb,
                          const float* __restrict__ wR) {
    __shared__ float sN[16 * 129];
    __shared__ float sW[16 * 129];
    __shared__ float sPF[16 * 6];
    __shared__ float sR[16 * 4];
    int t  = threadIdx.x;
    int o0 = blockIdx.x * 16;
    int s0 = blockIdx.y * 16;

    for (int e = t; e < 16 * 128; e += 256) {
        int r = e >> 7, k = e & 127;
        sN[r * 129 + k] = nodes[(s0 + r) * ND + k];
        sW[r * 129 + k] = wN[(o0 + r) * ND + k];
    }
    if (t < 16) {
        int s = s0 + t;
#pragma unroll
        for (int a = 0; a < 3; a++) {
            float v = 6.283185307179586f * pos[s * 3 + a];
            float sv, cv;
            sincosf(v, &sv, &cv);
            sPF[t * 6 + a]     = cv;
            sPF[t * 6 + 3 + a] = sv;
        }
#pragma unroll
        for (int a = 0; a < 4; a++) sR[t * 4 + a] = rotv[s * 4 + a];
    }
    __syncthreads();

    int tx = t & 15, ty = t >> 4;
    int o = o0 + tx;

    float aN = bNb[o];
    const float* nr = &sN[ty * 129];
    const float* wr = &sW[tx * 129];
#pragma unroll 8
    for (int k = 0; k < 128; k++) aN += nr[k] * wr[k];

    float aP = bPb[o];
#pragma unroll
    for (int k = 0; k < 6; k++) aP += sPF[ty * 6 + k] * wP[o * 6 + k];

    float aR = 0.f;
#pragma unroll
    for (int k = 0; k < 4; k++) aR += sR[ty * 4 + k] * wR[o * 4 + k];

    int hl = o >> 6, c = o & 63;
    int s = s0 + ty;
    int cc = c & 31;
    __nv_bfloat16* dh = (c < 32) ? g_Kh : g_Qh;
    __nv_bfloat16* dl = (c < 32) ? g_Kl : g_Ql;
    split_store(dh, dl, ((hl     ) * S + s) * DK + cc, aN);
    split_store(dh, dl, ((hl +  8) * S + s) * DK + cc, aP);
    split_store(dh, dl, ((hl + 16) * S + s) * DK + cc, aR);
}

// ---------------------------------------------------------------------------
// Flash attention via mma.sync bf16 (hi/lo split = ~fp32 accuracy).
// Block: 4 warps, i-tile 64 rows (16/warp), one head. j-tile 64.
// smem rows padded: K/Q 80B, V 272B -> conflict-free ldmatrix.
// ---------------------------------------------------------------------------
#define SK_H 0
#define SK_L 5120
#define SQ_H 10240
#define SQ_L 15360
#define SV_H 20480
#define SV_L 37888
#define SMEM_B 55296

__global__ void __launch_bounds__(128, 3) attn_mma(float* __restrict__ out) {
    extern __shared__ char sm[];
    const uint32_t sb = smem_u32(sm);
    const int t = threadIdx.x, wid = t >> 5, lane = t & 31;
    const int i0 = blockIdx.x * 64, h = blockIdx.y;
    const bool rot = (h >= 16);
    const int g = lane >> 3, lr = lane & 7;

    // K tile (once)
    for (int e = t; e < 256; e += 128) {
        int row = e >> 2, ch = e & 3;
        int gi = (h * S + i0 + row) * DK + ch * 8;
        *(uint4*)(sm + SK_H + row * 80 + ch * 16) = *(const uint4*)(g_Kh + gi);
        *(uint4*)(sm + SK_L + row * 80 + ch * 16) = *(const uint4*)(g_Kl + gi);
    }
    __syncthreads();

    const uint32_t aoff  = (uint32_t)((wid * 16 + (g & 1) * 8 + lr) * 80 + (g >> 1) * 16);
    const uint32_t qbase = (uint32_t)(((g >> 1) * 8 + lr) * 80 + (g & 1) * 16);
    const uint32_t vbase = (uint32_t)(((g >> 1) * 8 + lr) * 272 + (g & 1) * 16);

    uint32_t ah[2][4], al[2][4];
#pragma unroll
    for (int ks = 0; ks < 2; ks++) {
        ldsm4(ah[ks], sb + SK_H + aoff + ks * 32);
        ldsm4(al[ks], sb + SK_L + aoff + ks * 32);
    }

    float O[16][4];
#pragma unroll
    for (int nb = 0; nb < 16; nb++) O[nb][0] = O[nb][1] = O[nb][2] = O[nb][3] = 0.f;
    float Sa[8][4];
    float m0 = -1e30f, m1 = -1e30f, l0 = 0.f, l1 = 0.f;

    for (int jt = 0; jt < S / 64; jt++) {
        int j0 = jt * 64;
        __syncthreads();
        for (int e = t; e < 256; e += 128) {
            int row = e >> 2, ch = e & 3;
            int gi = (h * S + j0 + row) * DK + ch * 8;
            *(uint4*)(sm + SQ_H + row * 80 + ch * 16) = *(const uint4*)(g_Qh + gi);
            *(uint4*)(sm + SQ_L + row * 80 + ch * 16) = *(const uint4*)(g_Ql + gi);
        }
        for (int e = t; e < 1024; e += 128) {
            int row = e >> 4, ch = e & 15;
            int gi = (h * S + j0 + row) * DV + ch * 8;
            *(uint4*)(sm + SV_H + row * 272 + ch * 16) = *(const uint4*)(g_Vh + gi);
            *(uint4*)(sm + SV_L + row * 272 + ch * 16) = *(const uint4*)(g_Vl + gi);
        }
        __syncthreads();

        // ---- S = K . Q^T (3-term split) ----
#pragma unroll
        for (int nb = 0; nb < 8; nb++)
            Sa[nb][0] = Sa[nb][1] = Sa[nb][2] = Sa[nb][3] = 0.f;
#pragma unroll
        for (int n4 = 0; n4 < 4; n4++) {
#pragma unroll
            for (int ks = 0; ks < 2; ks++) {
                uint32_t qh[4], ql[4];
                ldsm4(qh, sb + SQ_H + qbase + n4 * 1280 + ks * 32);
                ldsm4(ql, sb + SQ_L + qbase + n4 * 1280 + ks * 32);
                mma16816(Sa[n4 * 2],     ah[ks], qh[0], qh[1]);
                mma16816(Sa[n4 * 2 + 1], ah[ks], qh[2], qh[3]);
                mma16816(Sa[n4 * 2],     al[ks], qh[0], qh[1]);
                mma16816(Sa[n4 * 2 + 1], al[ks], qh[2], qh[3]);
                mma16816(Sa[n4 * 2],     ah[ks], ql[0], ql[1]);
                mma16816(Sa[n4 * 2 + 1], ah[ks], ql[2], ql[3]);
            }
        }

        // ---- online softmax ----
        if (rot) {
#pragma unroll
            for (int nb = 0; nb < 8; nb++) {
                Sa[nb][0] *= Sa[nb][0]; Sa[nb][1] *= Sa[nb][1];
                Sa[nb][2] *= Sa[nb][2]; Sa[nb][3] *= Sa[nb][3];
            }
        }
        float mx0 = -1e30f, mx1 = -1e30f;
#pragma unroll
        for (int nb = 0; nb < 8; nb++) {
            mx0 = fmaxf(mx0, fmaxf(Sa[nb][0], Sa[nb][1]));
            mx1 = fmaxf(mx1, fmaxf(Sa[nb][2], Sa[nb][3]));
        }
        mx0 = fmaxf(mx0, __shfl_xor_sync(0xffffffffu, mx0, 1));
        mx0 = fmaxf(mx0, __shfl_xor_sync(0xffffffffu, mx0, 2));
        mx1 = fmaxf(mx1, __shfl_xor_sync(0xffffffffu, mx1, 1));
        mx1 = fmaxf(mx1, __shfl_xor_sync(0xffffffffu, mx1, 2));

        float mn0 = fmaxf(m0, mx0), mn1 = fmaxf(m1, mx1);
        float sc0 = fexp2((m0 - mn0) * L2E), sc1 = fexp2((m1 - mn1) * L2E);
        float b0 = mn0 * L2E, b1 = mn1 * L2E;
        float lp0 = 0.f, lp1 = 0.f;
#pragma unroll
        for (int nb = 0; nb < 8; nb++) {
            float p0 = fexp2(fmaf(Sa[nb][0], L2E, -b0));
            float p1 = fexp2(fmaf(Sa[nb][1], L2E, -b0));
            float p2 = fexp2(fmaf(Sa[nb][2], L2E, -b1));
            float p3 = fexp2(fmaf(Sa[nb][3], L2E, -b1));
            Sa[nb][0] = p0; Sa[nb][1] = p1; Sa[nb][2] = p2; Sa[nb][3] = p3;
            lp0 += p0 + p1; lp1 += p2 + p3;
        }
        l0 = l0 * sc0 + lp0;
        l1 = l1 * sc1 + lp1;
#pragma unroll
        for (int nb = 0; nb < 16; nb++) {
            O[nb][0] *= sc0; O[nb][1] *= sc0;
            O[nb][2] *= sc1; O[nb][3] *= sc1;
        }
        m0 = mn0; m1 = mn1;

        // ---- O += P . V (3-term split) ----
#pragma unroll
        for (int ks = 0; ks < 4; ks++) {
            uint32_t pah[4], pal[4];
#pragma unroll
            for (int u = 0; u < 4; u++) {
                const float* src = Sa[2 * ks + (u >> 1)];
                float x0 = src[(u & 1) * 2], x1 = src[(u & 1) * 2 + 1];
                __nv_bfloat16 h0 = __float2bfloat16_rn(x0);
                __nv_bfloat16 h1 = __float2bfloat16_rn(x1);
                __nv_bfloat162 hp; hp.x = h0; hp.y = h1;
                pah[u] = *reinterpret_cast<uint32_t*>(&hp);
                pal[u] = pack2(x0 - __bfloat162float(h0), x1 - __bfloat162float(h1));
            }
#pragma unroll
            for (int np = 0; np < 8; np++) {
                uint32_t vh[4], vl[4];
                ldsm4t(vh, sb + SV_H + vbase + ks * 4352 + np * 32);
                ldsm4t(vl, sb + SV_L + vbase + ks * 4352 + np * 32);
                mma16816(O[np * 2],     pah, vh[0], vh[2]);
                mma16816(O[np * 2 + 1], pah, vh[1], vh[3]);
                mma16816(O[np * 2],     pal, vh[0], vh[2]);
                mma16816(O[np * 2 + 1], pal, vh[1], vh[3]);
                mma16816(O[np * 2],     pah, vl[0], vl[2]);
                mma16816(O[np * 2 + 1], pah, vl[1], vl[3]);
            }
        }
    }

    // ---- epilogue: normalize + head-sum via atomics ----
    l0 += __shfl_xor_sync(0xffffffffu, l0, 1);
    l0 += __shfl_xor_sync(0xffffffffu, l0, 2);
    l1 += __shfl_xor_sync(0xffffffffu, l1, 1);
    l1 += __shfl_xor_sync(0xffffffffu, l1, 2);
    float inv0 = 1.0f / l0, inv1 = 1.0f / l1;
    int r0 = i0 + wid * 16 + (lane >> 2), r1 = r0 + 8;
    int cb = (lane & 3) * 2;
#pragma unroll
    for (int nb = 0; nb < 16; nb++) {
        int col = nb * 8 + cb;
        atomicAdd(&out[r0 * ND + col],     O[nb][0] * inv0);
        atomicAdd(&out[r0 * ND + col + 1], O[nb][1] * inv0);
        atomicAdd(&out[r1 * ND + col],     O[nb][2] * inv1);
        atomicAdd(&out[r1 * ND + col + 1], O[nb][3] * inv1);
    }
}

// ---------------------------------------------------------------------------
extern "C" void kernel_launch(void* const* d_in, const int* in_sizes, int n_in,
                              void* d_out, int out_size) {
    const float* nodes = (const float*)d_in[0];
    const float* pos   = (const float*)d_in[1];
    const float* rotv  = (const float*)d_in[2];
    const float* wN    = (const float*)d_in[3];
    const float* bN    = (const float*)d_in[4];
    const float* wP    = (const float*)d_in[5];
    const float* bP    = (const float*)d_in[6];
    const float* wR    = (const float*)d_in[7];
    const float* wV    = (const float*)d_in[8];
    const float* bV    = (const float*)d_in[9];
    float* out = (float*)d_out;

    zero_kernel<<<(S * ND + 255) / 256, 256>>>(out);
    val_kernel<<<dim3(3072 / 64, S / 16), 256>>>(nodes, wV, bV);
    kq_kernel<<<dim3(512 / 16, S / 16), 256>>>(nodes, pos, rotv, wN, bN, wP, bP, wR);

    cudaFuncSetAttribute(attn_mma, cudaFuncAttributeMaxDynamicSharedMemorySize, SMEM_B);
    attn_mma<<<dim3(S / 64, NH), 128, SMEM_B>>>(out);
}

// round 14
// speedup vs baseline: 2.8745x; 1.0448x over previous
#include <cuda_runtime.h>
#include <cuda_bf16.h>
#include <stdint.h>
#include <math.h>

#define S   2048
#define ND  128
#define NH  24
#define DK  32
#define DV  128
#define L2E 1.4426950408889634f

// hi/lo bf16 split operands (device globals — no allocation allowed)
__device__ __nv_bfloat16 g_Kh[NH * S * DK], g_Kl[NH * S * DK];   // [h][s][c]
__device__ __nv_bfloat16 g_Qh[NH * S * DK], g_Ql[NH * S * DK];   // [h][s][c]
__device__ __nv_bfloat16 g_Vh[NH * S * DV], g_Vl[NH * S * DV];   // [h][s][d]

// ---------------------------------------------------------------------------
static __device__ __forceinline__ uint32_t smem_u32(const void* p) {
    uint32_t a;
    asm("{ .reg .u64 t; cvta.to.shared.u64 t, %1; cvt.u32.u64 %0, t; }" : "=r"(a) : "l"(p));
    return a;
}
static __device__ __forceinline__ void ldsm4(uint32_t* r, uint32_t a) {
    asm volatile("ldmatrix.sync.aligned.m8n8.x4.shared.b16 {%0,%1,%2,%3}, [%4];"
                 : "=r"(r[0]), "=r"(r[1]), "=r"(r[2]), "=r"(r[3]) : "r"(a));
}
static __device__ __forceinline__ void ldsm4t(uint32_t* r, uint32_t a) {
    asm volatile("ldmatrix.sync.aligned.m8n8.x4.trans.shared.b16 {%0,%1,%2,%3}, [%4];"
                 : "=r"(r[0]), "=r"(r[1]), "=r"(r[2]), "=r"(r[3]) : "r"(a));
}
static __device__ __forceinline__ void mma16816(float* d, const uint32_t* a,
                                                uint32_t b0, uint32_t b1) {
    asm volatile("mma.sync.aligned.m16n8k16.row.col.f32.bf16.bf16.f32 "
                 "{%0,%1,%2,%3}, {%4,%5,%6,%7}, {%8,%9}, {%0,%1,%2,%3};"
                 : "+f"(d[0]), "+f"(d[1]), "+f"(d[2]), "+f"(d[3])
                 : "r"(a[0]), "r"(a[1]), "r"(a[2]), "r"(a[3]), "r"(b0), "r"(b1));
}

// fast exp2 on the FMA pipe (no MUFU). |rel err| ~2e-6.
static __device__ __forceinline__ float fexp2(float y) {
    y = fmaxf(y, -120.0f);
    float t = y + 12582912.0f;
    int   n = __float_as_int(t) << 23;
    float f = y - (t - 12582912.0f);
    float p =              1.3333558e-3f;
    p = fmaf(p, f, 9.6181291e-3f);
    p = fmaf(p, f, 5.5504109e-2f);
    p = fmaf(p, f, 2.4022651e-1f);
    p = fmaf(p, f, 6.9314718e-1f);
    p = fmaf(p, f, 1.0f);
    return __int_as_float(__float_as_int(p) + n);
}

static __device__ __forceinline__ void split_store(__nv_bfloat16* ph, __nv_bfloat16* pl,
                                                   int idx, float x) {
    __nv_bfloat16 hv = __float2bfloat16_rn(x);
    ph[idx] = hv;
    pl[idx] = __float2bfloat16_rn(x - __bfloat162float(hv));
}
static __device__ __forceinline__ uint32_t pack2(float a, float b) {
    __nv_bfloat162 v = __floats2bfloat162_rn(a, b);   // a -> low, b -> high
    return *reinterpret_cast<uint32_t*>(&v);
}

// ---------------------------------------------------------------------------
__global__ void zero_kernel(float* out) {
    int i = blockIdx.x * blockDim.x + threadIdx.x;
    if (i < S * ND) out[i] = 0.f;
}

// ---------------------------------------------------------------------------
// P1: values GEMM -> split bf16 g_Vh/g_Vl [h][s][d]
// row pad 132 floats (528 B, 16B-aligned) -> float4 LDS, conflict-free
// ---------------------------------------------------------------------------
__global__ void val_kernel(const float* __restrict__ nodes,
                           const float* __restrict__ wV,
                           const float* __restrict__ bV) {
    __shared__ float sA[16 * 132];
    __shared__ float sW[64 * 132];
    int t  = threadIdx.x;
    int o0 = blockIdx.x * 64;
    int s0 = blockIdx.y * 16;

    for (int e = t; e < 16 * 128; e += 256) {
        int r = e >> 7, k = e & 127;
        sA[r * 132 + k] = nodes[(s0 + r) * ND + k];
    }
    for (int e = t; e < 64 * 128; e += 256) {
        int r = e >> 7, k = e & 127;
        sW[r * 132 + k] = wV[(o0 + r) * ND + k];
    }
    __syncthreads();

    int tx = t & 15, ty = t >> 4;
    float a0 = bV[o0 + tx];
    float a1 = bV[o0 + tx + 16];
    float a2 = bV[o0 + tx + 32];
    float a3 = bV[o0 + tx + 48];
    const float4* a4 = (const float4*)&sA[ty * 132];
    const float4* w0 = (const float4*)&sW[(tx     ) * 132];
    const float4* w1 = (const float4*)&sW[(tx + 16) * 132];
    const float4* w2 = (const float4*)&sW[(tx + 32) * 132];
    const float4* w3 = (const float4*)&sW[(tx + 48) * 132];
#pragma unroll 8
    for (int k = 0; k < 32; k++) {
        float4 a = a4[k];
        float4 b0 = w0[k], b1 = w1[k], b2 = w2[k], b3 = w3[k];
        a0 += a.x * b0.x + a.y * b0.y + a.z * b0.z + a.w * b0.w;
        a1 += a.x * b1.x + a.y * b1.y + a.z * b1.z + a.w * b1.w;
        a2 += a.x * b2.x + a.y * b2.y + a.z * b2.z + a.w * b2.w;
        a3 += a.x * b3.x + a.y * b3.y + a.z * b3.z + a.w * b3.w;
    }
    int s = s0 + ty;
#pragma unroll
    for (int u = 0; u < 4; u++) {
        float v = (u == 0) ? a0 : (u == 1) ? a1 : (u == 2) ? a2 : a3;
        int o = o0 + tx + u * 16;
        int hh = o >> 7, d = o & 127;
        split_store(g_Vh, g_Vl, (hh * S + s) * DV + d, v);
    }
}

// ---------------------------------------------------------------------------
// P2: K/Q projections -> split bf16 g_K*/g_Q* [h][s][c]
// ---------------------------------------------------------------------------
__global__ void kq_kernel(const float* __restrict__ nodes,
                          const float* __restrict__ pos,
                          const float* __restrict__ rotv,
                          const float* __restrict__ wN, const float* __restrict__ bNb,
                          const float* __restrict__ wP, const float* __restrict__ bPb,
                          const float* __restrict__ wR) {
    __shared__ float sN[16 * 132];
    __shared__ float sW[16 * 132];
    __shared__ float sPF[16 * 6];
    __shared__ float sR[16 * 4];
    int t  = threadIdx.x;
    int o0 = blockIdx.x * 16;
    int s0 = blockIdx.y * 16;

    for (int e = t; e < 16 * 128; e += 256) {
        int r = e >> 7, k = e & 127;
        sN[r * 132 + k] = nodes[(s0 + r) * ND + k];
        sW[r * 132 + k] = wN[(o0 + r) * ND + k];
    }
    if (t < 16) {
        int s = s0 + t;
#pragma unroll
        for (int a = 0; a < 3; a++) {
            float v = 6.283185307179586f * pos[s * 3 + a];
            float sv, cv;
            sincosf(v, &sv, &cv);
            sPF[t * 6 + a]     = cv;
            sPF[t * 6 + 3 + a] = sv;
        }
#pragma unroll
        for (int a = 0; a < 4; a++) sR[t * 4 + a] = rotv[s * 4 + a];
    }
    __syncthreads();

    int tx = t & 15, ty = t >> 4;
    int o = o0 + tx;

    float aN = bNb[o];
    const float4* n4 = (const float4*)&sN[ty * 132];
    const float4* w4 = (const float4*)&sW[tx * 132];
#pragma unroll 8
    for (int k = 0; k < 32; k++) {
        float4 a = n4[k], b = w4[k];
        aN += a.x * b.x + a.y * b.y + a.z * b.z + a.w * b.w;
    }

    float aP = bPb[o];
#pragma unroll
    for (int k = 0; k < 6; k++) aP += sPF[ty * 6 + k] * wP[o * 6 + k];

    float aR = 0.f;
#pragma unroll
    for (int k = 0; k < 4; k++) aR += sR[ty * 4 + k] * wR[o * 4 + k];

    int hl = o >> 6, c = o & 63;
    int s = s0 + ty;
    int cc = c & 31;
    __nv_bfloat16* dh = (c < 32) ? g_Kh : g_Qh;
    __nv_bfloat16* dl = (c < 32) ? g_Kl : g_Ql;
    split_store(dh, dl, ((hl     ) * S + s) * DK + cc, aN);
    split_store(dh, dl, ((hl +  8) * S + s) * DK + cc, aP);
    split_store(dh, dl, ((hl + 16) * S + s) * DK + cc, aR);
}

// ---------------------------------------------------------------------------
// Flash attention via mma.sync bf16 (hi/lo split = ~fp32 accuracy).
// Term-major MMA ordering: 8 independent accumulator chains between reuses.
// ---------------------------------------------------------------------------
#define SK_H 0
#define SK_L 5120
#define SQ_H 10240
#define SQ_L 15360
#define SV_H 20480
#define SV_L 37888
#define SMEM_B 55296

__global__ void __launch_bounds__(128, 3) attn_mma(float* __restrict__ out) {
    extern __shared__ char sm[];
    const uint32_t sb = smem_u32(sm);
    const int t = threadIdx.x, wid = t >> 5, lane = t & 31;
    const int i0 = blockIdx.x * 64, h = blockIdx.y;
    const bool rot = (h >= 16);
    const int g = lane >> 3, lr = lane & 7;

    // K tile (once)
    for (int e = t; e < 256; e += 128) {
        int row = e >> 2, ch = e & 3;
        int gi = (h * S + i0 + row) * DK + ch * 8;
        *(uint4*)(sm + SK_H + row * 80 + ch * 16) = *(const uint4*)(g_Kh + gi);
        *(uint4*)(sm + SK_L + row * 80 + ch * 16) = *(const uint4*)(g_Kl + gi);
    }
    __syncthreads();

    const uint32_t aoff  = (uint32_t)((wid * 16 + (g & 1) * 8 + lr) * 80 + (g >> 1) * 16);
    const uint32_t qbase = (uint32_t)(((g >> 1) * 8 + lr) * 80 + (g & 1) * 16);
    const uint32_t vbase = (uint32_t)(((g >> 1) * 8 + lr) * 272 + (g & 1) * 16);

    uint32_t ah[2][4], al[2][4];
#pragma unroll
    for (int ks = 0; ks < 2; ks++) {
        ldsm4(ah[ks], sb + SK_H + aoff + ks * 32);
        ldsm4(al[ks], sb + SK_L + aoff + ks * 32);
    }

    float O[16][4];
#pragma unroll
    for (int nb = 0; nb < 16; nb++) O[nb][0] = O[nb][1] = O[nb][2] = O[nb][3] = 0.f;
    float Sa[8][4];
    float m0 = -1e30f, m1 = -1e30f, l0 = 0.f, l1 = 0.f;

    for (int jt = 0; jt < S / 64; jt++) {
        int j0 = jt * 64;
        __syncthreads();
        for (int e = t; e < 256; e += 128) {
            int row = e >> 2, ch = e & 3;
            int gi = (h * S + j0 + row) * DK + ch * 8;
            *(uint4*)(sm + SQ_H + row * 80 + ch * 16) = *(const uint4*)(g_Qh + gi);
            *(uint4*)(sm + SQ_L + row * 80 + ch * 16) = *(const uint4*)(g_Ql + gi);
        }
        for (int e = t; e < 1024; e += 128) {
            int row = e >> 4, ch = e & 15;
            int gi = (h * S + j0 + row) * DV + ch * 8;
            *(uint4*)(sm + SV_H + row * 272 + ch * 16) = *(const uint4*)(g_Vh + gi);
            *(uint4*)(sm + SV_L + row * 272 + ch * 16) = *(const uint4*)(g_Vl + gi);
        }
        __syncthreads();

        // ---- S = K . Q^T (3-term split, term-major for 8-way ILP) ----
#pragma unroll
        for (int nb = 0; nb < 8; nb++)
            Sa[nb][0] = Sa[nb][1] = Sa[nb][2] = Sa[nb][3] = 0.f;
#pragma unroll
        for (int ks = 0; ks < 2; ks++) {
            uint32_t qh[4][4], ql[4][4];
#pragma unroll
            for (int n4 = 0; n4 < 4; n4++) {
                ldsm4(qh[n4], sb + SQ_H + qbase + n4 * 1280 + ks * 32);
                ldsm4(ql[n4], sb + SQ_L + qbase + n4 * 1280 + ks * 32);
            }
#pragma unroll
            for (int n4 = 0; n4 < 4; n4++) {
                mma16816(Sa[n4 * 2],     ah[ks], qh[n4][0], qh[n4][1]);
                mma16816(Sa[n4 * 2 + 1], ah[ks], qh[n4][2], qh[n4][3]);
            }
#pragma unroll
            for (int n4 = 0; n4 < 4; n4++) {
                mma16816(Sa[n4 * 2],     al[ks], qh[n4][0], qh[n4][1]);
                mma16816(Sa[n4 * 2 + 1], al[ks], qh[n4][2], qh[n4][3]);
            }
#pragma unroll
            for (int n4 = 0; n4 < 4; n4++) {
                mma16816(Sa[n4 * 2],     ah[ks], ql[n4][0], ql[n4][1]);
                mma16816(Sa[n4 * 2 + 1], ah[ks], ql[n4][2], ql[n4][3]);
            }
        }

        // ---- online softmax ----
        if (rot) {
#pragma unroll
            for (int nb = 0; nb < 8; nb++) {
                Sa[nb][0] *= Sa[nb][0]; Sa[nb][1] *= Sa[nb][1];
                Sa[nb][2] *= Sa[nb][2]; Sa[nb][3] *= Sa[nb][3];
            }
        }
        float mx0 = -1e30f, mx1 = -1e30f;
#pragma unroll
        for (int nb = 0; nb < 8; nb++) {
            mx0 = fmaxf(mx0, fmaxf(Sa[nb][0], Sa[nb][1]));
            mx1 = fmaxf(mx1, fmaxf(Sa[nb][2], Sa[nb][3]));
        }
        mx0 = fmaxf(mx0, __shfl_xor_sync(0xffffffffu, mx0, 1));
        mx0 = fmaxf(mx0, __shfl_xor_sync(0xffffffffu, mx0, 2));
        mx1 = fmaxf(mx1, __shfl_xor_sync(0xffffffffu, mx1, 1));
        mx1 = fmaxf(mx1, __shfl_xor_sync(0xffffffffu, mx1, 2));

        float mn0 = fmaxf(m0, mx0), mn1 = fmaxf(m1, mx1);
        float sc0 = fexp2((m0 - mn0) * L2E), sc1 = fexp2((m1 - mn1) * L2E);
        float b0 = mn0 * L2E, b1 = mn1 * L2E;
        float lp0 = 0.f, lp1 = 0.f;
#pragma unroll
        for (int nb = 0; nb < 8; nb++) {
            float p0 = fexp2(fmaf(Sa[nb][0], L2E, -b0));
            float p1 = fexp2(fmaf(Sa[nb][1], L2E, -b0));
            float p2 = fexp2(fmaf(Sa[nb][2], L2E, -b1));
            float p3 = fexp2(fmaf(Sa[nb][3], L2E, -b1));
            Sa[nb][0] = p0; Sa[nb][1] = p1; Sa[nb][2] = p2; Sa[nb][3] = p3;
            lp0 += p0 + p1; lp1 += p2 + p3;
        }
        l0 = l0 * sc0 + lp0;
        l1 = l1 * sc1 + lp1;
#pragma unroll
        for (int nb = 0; nb < 16; nb++) {
            O[nb][0] *= sc0; O[nb][1] *= sc0;
            O[nb][2] *= sc1; O[nb][3] *= sc1;
        }
        m0 = mn0; m1 = mn1;

        // ---- O += P . V (3-term split, term-major, np in groups of 4) ----
#pragma unroll
        for (int ks = 0; ks < 4; ks++) {
            uint32_t pah[4], pal[4];
#pragma unroll
            for (int u = 0; u < 4; u++) {
                const float* src = Sa[2 * ks + (u >> 1)];
                float x0 = src[(u & 1) * 2], x1 = src[(u & 1) * 2 + 1];
                __nv_bfloat16 h0 = __float2bfloat16_rn(x0);
                __nv_bfloat16 h1 = __float2bfloat16_rn(x1);
                __nv_bfloat162 hp; hp.x = h0; hp.y = h1;
                pah[u] = *reinterpret_cast<uint32_t*>(&hp);
                pal[u] = pack2(x0 - __bfloat162float(h0), x1 - __bfloat162float(h1));
            }
#pragma unroll
            for (int grp = 0; grp < 2; grp++) {
                uint32_t vh[4][4], vl[4][4];
#pragma unroll
                for (int j = 0; j < 4; j++) {
                    int np = grp * 4 + j;
                    ldsm4t(vh[j], sb + SV_H + vbase + ks * 4352 + np * 32);
                    ldsm4t(vl[j], sb + SV_L + vbase + ks * 4352 + np * 32);
                }
#pragma unroll
                for (int j = 0; j < 4; j++) {
                    int np = grp * 4 + j;
                    mma16816(O[np * 2],     pah, vh[j][0], vh[j][2]);
                    mma16816(O[np * 2 + 1], pah, vh[j][1], vh[j][3]);
                }
#pragma unroll
                for (int j = 0; j < 4; j++) {
                    int np = grp * 4 + j;
                    mma16816(O[np * 2],     pal, vh[j][0], vh[j][2]);
                    mma16816(O[np * 2 + 1], pal, vh[j][1], vh[j][3]);
                }
#pragma unroll
                for (int j = 0; j < 4; j++) {
                    int np = grp * 4 + j;
                    mma16816(O[np * 2],     pah, vl[j][0], vl[j][2]);
                    mma16816(O[np * 2 + 1], pah, vl[j][1], vl[j][3]);
                }
            }
        }
    }

    // ---- epilogue: normalize + head-sum via atomics ----
    l0 += __shfl_xor_sync(0xffffffffu, l0, 1);
    l0 += __shfl_xor_sync(0xffffffffu, l0, 2);
    l1 += __shfl_xor_sync(0xffffffffu, l1, 1);
    l1 += __shfl_xor_sync(0xffffffffu, l1, 2);
    float inv0 = 1.0f / l0, inv1 = 1.0f / l1;
    int r0 = i0 + wid * 16 + (lane >> 2), r1 = r0 + 8;
    int cb = (lane & 3) * 2;
#pragma unroll
    for (int nb = 0; nb < 16; nb++) {
        int col = nb * 8 + cb;
        atomicAdd(&out[r0 * ND + col],     O[nb][0] * inv0);
        atomicAdd(&out[r0 * ND + col + 1], O[nb][1] * inv0);
        atomicAdd(&out[r1 * ND + col],     O[nb][2] * inv1);
        atomicAdd(&out[r1 * ND + col + 1], O[nb][3] * inv1);
    }
}

// ---------------------------------------------------------------------------
extern "C" void kernel_launch(void* const* d_in, const int* in_sizes, int n_in,
                              void* d_out, int out_size) {
    const float* nodes = (const float*)d_in[0];
    const float* pos   = (const float*)d_in[1];
    const float* rotv  = (const float*)d_in[2];
    const float* wN    = (const float*)d_in[3];
    const float* bN    = (const float*)d_in[4];
    const float* wP    = (const float*)d_in[5];
    const float* bP    = (const float*)d_in[6];
    const float* wR    = (const float*)d_in[7];
    const float* wV    = (const float*)d_in[8];
    const float* bV    = (const float*)d_in[9];
    float* out = (float*)d_out;

    zero_kernel<<<(S * ND + 255) / 256, 256>>>(out);
    val_kernel<<<dim3(3072 / 64, S / 16), 256>>>(nodes, wV, bV);
    kq_kernel<<<dim3(512 / 16, S / 16), 256>>>(nodes, pos, rotv, wN, bN, wP, bP, wR);

    cudaFuncSetAttribute(attn_mma, cudaFuncAttributeMaxDynamicSharedMemorySize, SMEM_B);
    attn_mma<<<dim3(S / 64, NH), 128, SMEM_B>>>(out);
}

// round 15
// speedup vs baseline: 3.4156x; 1.1882x over previous
#include <cuda_runtime.h>
#include <cuda_bf16.h>
#include <stdint.h>
#include <math.h>

#define S   2048
#define ND  128
#define NH  24
#define DK  32
#define DV  128
#define L2E 1.4426950408889634f

// hi/lo bf16 split operands (device globals — no allocation allowed)
__device__ __nv_bfloat16 g_Kh[NH * S * DK], g_Kl[NH * S * DK];   // [h][s][c]
__device__ __nv_bfloat16 g_Qh[NH * S * DK], g_Ql[NH * S * DK];   // [h][s][c]
__device__ __nv_bfloat16 g_Vh[NH * S * DV], g_Vl[NH * S * DV];   // [h][s][d]

// ---------------------------------------------------------------------------
static __device__ __forceinline__ uint32_t smem_u32(const void* p) {
    uint32_t a;
    asm("{ .reg .u64 t; cvta.to.shared.u64 t, %1; cvt.u32.u64 %0, t; }" : "=r"(a) : "l"(p));
    return a;
}
static __device__ __forceinline__ void ldsm4(uint32_t* r, uint32_t a) {
    asm volatile("ldmatrix.sync.aligned.m8n8.x4.shared.b16 {%0,%1,%2,%3}, [%4];"
                 : "=r"(r[0]), "=r"(r[1]), "=r"(r[2]), "=r"(r[3]) : "r"(a));
}
static __device__ __forceinline__ void ldsm4t(uint32_t* r, uint32_t a) {
    asm volatile("ldmatrix.sync.aligned.m8n8.x4.trans.shared.b16 {%0,%1,%2,%3}, [%4];"
                 : "=r"(r[0]), "=r"(r[1]), "=r"(r[2]), "=r"(r[3]) : "r"(a));
}
static __device__ __forceinline__ void mma16816(float* d, const uint32_t* a,
                                                uint32_t b0, uint32_t b1) {
    asm volatile("mma.sync.aligned.m16n8k16.row.col.f32.bf16.bf16.f32 "
                 "{%0,%1,%2,%3}, {%4,%5,%6,%7}, {%8,%9}, {%0,%1,%2,%3};"
                 : "+f"(d[0]), "+f"(d[1]), "+f"(d[2]), "+f"(d[3])
                 : "r"(a[0]), "r"(a[1]), "r"(a[2]), "r"(a[3]), "r"(b0), "r"(b1));
}

// fast exp2 on the FMA pipe (no MUFU). |rel err| ~2e-6.
static __device__ __forceinline__ float fexp2(float y) {
    y = fmaxf(y, -120.0f);
    float t = y + 12582912.0f;
    int   n = __float_as_int(t) << 23;
    float f = y - (t - 12582912.0f);
    float p =              1.3333558e-3f;
    p = fmaf(p, f, 9.6181291e-3f);
    p = fmaf(p, f, 5.5504109e-2f);
    p = fmaf(p, f, 2.4022651e-1f);
    p = fmaf(p, f, 6.9314718e-1f);
    p = fmaf(p, f, 1.0f);
    return __int_as_float(__float_as_int(p) + n);
}

static __device__ __forceinline__ void split_store(__nv_bfloat16* ph, __nv_bfloat16* pl,
                                                   int idx, float x) {
    __nv_bfloat16 hv = __float2bfloat16_rn(x);
    ph[idx] = hv;
    pl[idx] = __float2bfloat16_rn(x - __bfloat162float(hv));
}
static __device__ __forceinline__ uint32_t pack2(float a, float b) {
    __nv_bfloat162 v = __floats2bfloat162_rn(a, b);   // a -> low, b -> high
    return *reinterpret_cast<uint32_t*>(&v);
}
static __device__ __forceinline__ float dot4(float4 a, float4 b) {
    return a.x * b.x + a.y * b.y + a.z * b.z + a.w * b.w;
}

// ---------------------------------------------------------------------------
__global__ void zero_kernel(float* out) {
    int i = blockIdx.x * blockDim.x + threadIdx.x;
    if (i < S * ND) out[i] = 0.f;
}

// ---------------------------------------------------------------------------
// P1: values GEMM -> split bf16 g_Vh/g_Vl [h][s][d]
// 64x64 tile, 4x4 outputs/thread: 8 float4 LDS per 64 FMA (byte-traffic bound fix)
// ---------------------------------------------------------------------------
#define VAL_SMEM (2 * 64 * 132 * 4)

__global__ void val_kernel(const float* __restrict__ nodes,
                           const float* __restrict__ wV,
                           const float* __restrict__ bV) {
    extern __shared__ float vsm[];
    float* sA = vsm;             // 64 x 132
    float* sW = vsm + 64 * 132;  // 64 x 132
    int t  = threadIdx.x;
    int o0 = blockIdx.x * 64;
    int s0 = blockIdx.y * 64;

    for (int e = t; e < 64 * 32; e += 256) {
        int r = e >> 5, k4 = e & 31;
        *(float4*)&sA[r * 132 + k4 * 4] = *(const float4*)&nodes[(s0 + r) * ND + k4 * 4];
        *(float4*)&sW[r * 132 + k4 * 4] = *(const float4*)&wV[(o0 + r) * ND + k4 * 4];
    }
    __syncthreads();

    int tx = t & 15, ty = t >> 4;
    float acc[4][4];
#pragma unroll
    for (int v = 0; v < 4; v++) {
        float b = bV[o0 + tx + 16 * v];
#pragma unroll
        for (int u = 0; u < 4; u++) acc[u][v] = b;
    }

#pragma unroll 4
    for (int k4 = 0; k4 < 32; k4++) {
        float4 a[4], w[4];
#pragma unroll
        for (int u = 0; u < 4; u++) a[u] = *(const float4*)&sA[(ty + 16 * u) * 132 + k4 * 4];
#pragma unroll
        for (int v = 0; v < 4; v++) w[v] = *(const float4*)&sW[(tx + 16 * v) * 132 + k4 * 4];
#pragma unroll
        for (int u = 0; u < 4; u++)
#pragma unroll
            for (int v = 0; v < 4; v++)
                acc[u][v] += dot4(a[u], w[v]);
    }

#pragma unroll
    for (int u = 0; u < 4; u++) {
        int s = s0 + ty + 16 * u;
#pragma unroll
        for (int v = 0; v < 4; v++) {
            int o = o0 + tx + 16 * v;
            int hh = o >> 7, d = o & 127;
            split_store(g_Vh, g_Vl, (hh * S + s) * DV + d, acc[u][v]);
        }
    }
}

// ---------------------------------------------------------------------------
// P2: K/Q projections -> split bf16 g_K*/g_Q* [h][s][c]
// 32x32 tile, 2x2 outputs/thread (LDS bytes halved)
// ---------------------------------------------------------------------------
__global__ void kq_kernel(const float* __restrict__ nodes,
                          const float* __restrict__ pos,
                          const float* __restrict__ rotv,
                          const float* __restrict__ wN, const float* __restrict__ bNb,
                          const float* __restrict__ wP, const float* __restrict__ bPb,
                          const float* __restrict__ wR) {
    __shared__ float sN[32 * 132];
    __shared__ float sW[32 * 132];
    __shared__ float sPF[32 * 6];
    __shared__ float sR[32 * 4];
    int t  = threadIdx.x;
    int o0 = blockIdx.x * 32;
    int s0 = blockIdx.y * 32;

    for (int e = t; e < 32 * 32; e += 256) {
        int r = e >> 5, k4 = e & 31;
        *(float4*)&sN[r * 132 + k4 * 4] = *(const float4*)&nodes[(s0 + r) * ND + k4 * 4];
        *(float4*)&sW[r * 132 + k4 * 4] = *(const float4*)&wN[(o0 + r) * ND + k4 * 4];
    }
    if (t < 32) {
        int s = s0 + t;
#pragma unroll
        for (int a = 0; a < 3; a++) {
            float v = 6.283185307179586f * pos[s * 3 + a];
            float sv, cv;
            sincosf(v, &sv, &cv);
            sPF[t * 6 + a]     = cv;
            sPF[t * 6 + 3 + a] = sv;
        }
#pragma unroll
        for (int a = 0; a < 4; a++) sR[t * 4 + a] = rotv[s * 4 + a];
    }
    __syncthreads();

    int tx = t & 15, ty = t >> 4;
    float aN[2][2];
#pragma unroll
    for (int v = 0; v < 2; v++) {
        float b = bNb[o0 + tx + 16 * v];
        aN[0][v] = b; aN[1][v] = b;
    }
#pragma unroll 4
    for (int k4 = 0; k4 < 32; k4++) {
        float4 a0 = *(const float4*)&sN[(ty     ) * 132 + k4 * 4];
        float4 a1 = *(const float4*)&sN[(ty + 16) * 132 + k4 * 4];
        float4 w0 = *(const float4*)&sW[(tx     ) * 132 + k4 * 4];
        float4 w1 = *(const float4*)&sW[(tx + 16) * 132 + k4 * 4];
        aN[0][0] += dot4(a0, w0); aN[0][1] += dot4(a0, w1);
        aN[1][0] += dot4(a1, w0); aN[1][1] += dot4(a1, w1);
    }

#pragma unroll
    for (int u = 0; u < 2; u++) {
        int sl = ty + 16 * u;
        int s = s0 + sl;
#pragma unroll
        for (int v = 0; v < 2; v++) {
            int o = o0 + tx + 16 * v;

            float aP = bPb[o];
#pragma unroll
            for (int k = 0; k < 6; k++) aP += sPF[sl * 6 + k] * wP[o * 6 + k];

            float aR = 0.f;
#pragma unroll
            for (int k = 0; k < 4; k++) aR += sR[sl * 4 + k] * wR[o * 4 + k];

            int hl = o >> 6, c = o & 63;
            int cc = c & 31;
            __nv_bfloat16* dh = (c < 32) ? g_Kh : g_Qh;
            __nv_bfloat16* dl = (c < 32) ? g_Kl : g_Ql;
            split_store(dh, dl, ((hl     ) * S + s) * DK + cc, aN[u][v]);
            split_store(dh, dl, ((hl +  8) * S + s) * DK + cc, aP);
            split_store(dh, dl, ((hl + 16) * S + s) * DK + cc, aR);
        }
    }
}

// ---------------------------------------------------------------------------
// Flash attention via mma.sync bf16 (hi/lo split = ~fp32 accuracy).
// UNCHANGED from the 359us-passing R14 version (near HMMA throughput ceiling).
// ---------------------------------------------------------------------------
#define SK_H 0
#define SK_L 5120
#define SQ_H 10240
#define SQ_L 15360
#define SV_H 20480
#define SV_L 37888
#define SMEM_B 55296

__global__ void __launch_bounds__(128, 3) attn_mma(float* __restrict__ out) {
    extern __shared__ char sm[];
    const uint32_t sb = smem_u32(sm);
    const int t = threadIdx.x, wid = t >> 5, lane = t & 31;
    const int i0 = blockIdx.x * 64, h = blockIdx.y;
    const bool rot = (h >= 16);
    const int g = lane >> 3, lr = lane & 7;

    // K tile (once)
    for (int e = t; e < 256; e += 128) {
        int row = e >> 2, ch = e & 3;
        int gi = (h * S + i0 + row) * DK + ch * 8;
        *(uint4*)(sm + SK_H + row * 80 + ch * 16) = *(const uint4*)(g_Kh + gi);
        *(uint4*)(sm + SK_L + row * 80 + ch * 16) = *(const uint4*)(g_Kl + gi);
    }
    __syncthreads();

    const uint32_t aoff  = (uint32_t)((wid * 16 + (g & 1) * 8 + lr) * 80 + (g >> 1) * 16);
    const uint32_t qbase = (uint32_t)(((g >> 1) * 8 + lr) * 80 + (g & 1) * 16);
    const uint32_t vbase = (uint32_t)(((g >> 1) * 8 + lr) * 272 + (g & 1) * 16);

    uint32_t ah[2][4], al[2][4];
#pragma unroll
    for (int ks = 0; ks < 2; ks++) {
        ldsm4(ah[ks], sb + SK_H + aoff + ks * 32);
        ldsm4(al[ks], sb + SK_L + aoff + ks * 32);
    }

    float O[16][4];
#pragma unroll
    for (int nb = 0; nb < 16; nb++) O[nb][0] = O[nb][1] = O[nb][2] = O[nb][3] = 0.f;
    float Sa[8][4];
    float m0 = -1e30f, m1 = -1e30f, l0 = 0.f, l1 = 0.f;

    for (int jt = 0; jt < S / 64; jt++) {
        int j0 = jt * 64;
        __syncthreads();
        for (int e = t; e < 256; e += 128) {
            int row = e >> 2, ch = e & 3;
            int gi = (h * S + j0 + row) * DK + ch * 8;
            *(uint4*)(sm + SQ_H + row * 80 + ch * 16) = *(const uint4*)(g_Qh + gi);
            *(uint4*)(sm + SQ_L + row * 80 + ch * 16) = *(const uint4*)(g_Ql + gi);
        }
        for (int e = t; e < 1024; e += 128) {
            int row = e >> 4, ch = e & 15;
            int gi = (h * S + j0 + row) * DV + ch * 8;
            *(uint4*)(sm + SV_H + row * 272 + ch * 16) = *(const uint4*)(g_Vh + gi);
            *(uint4*)(sm + SV_L + row * 272 + ch * 16) = *(const uint4*)(g_Vl + gi);
        }
        __syncthreads();

        // ---- S = K . Q^T (3-term split) ----
#pragma unroll
        for (int nb = 0; nb < 8; nb++)
            Sa[nb][0] = Sa[nb][1] = Sa[nb][2] = Sa[nb][3] = 0.f;
#pragma unroll
        for (int ks = 0; ks < 2; ks++) {
            uint32_t qh[4][4], ql[4][4];
#pragma unroll
            for (int n4 = 0; n4 < 4; n4++) {
                ldsm4(qh[n4], sb + SQ_H + qbase + n4 * 1280 + ks * 32);
                ldsm4(ql[n4], sb + SQ_L + qbase + n4 * 1280 + ks * 32);
            }
#pragma unroll
            for (int n4 = 0; n4 < 4; n4++) {
                mma16816(Sa[n4 * 2],     ah[ks], qh[n4][0], qh[n4][1]);
                mma16816(Sa[n4 * 2 + 1], ah[ks], qh[n4][2], qh[n4][3]);
            }
#pragma unroll
            for (int n4 = 0; n4 < 4; n4++) {
                mma16816(Sa[n4 * 2],     al[ks], qh[n4][0], qh[n4][1]);
                mma16816(Sa[n4 * 2 + 1], al[ks], qh[n4][2], qh[n4][3]);
            }
#pragma unroll
            for (int n4 = 0; n4 < 4; n4++) {
                mma16816(Sa[n4 * 2],     ah[ks], ql[n4][0], ql[n4][1]);
                mma16816(Sa[n4 * 2 + 1], ah[ks], ql[n4][2], ql[n4][3]);
            }
        }

        // ---- online softmax ----
        if (rot) {
#pragma unroll
            for (int nb = 0; nb < 8; nb++) {
                Sa[nb][0] *= Sa[nb][0]; Sa[nb][1] *= Sa[nb][1];
                Sa[nb][2] *= Sa[nb][2]; Sa[nb][3] *= Sa[nb][3];
            }
        }
        float mx0 = -1e30f, mx1 = -1e30f;
#pragma unroll
        for (int nb = 0; nb < 8; nb++) {
            mx0 = fmaxf(mx0, fmaxf(Sa[nb][0], Sa[nb][1]));
            mx1 = fmaxf(mx1, fmaxf(Sa[nb][2], Sa[nb][3]));
        }
        mx0 = fmaxf(mx0, __shfl_xor_sync(0xffffffffu, mx0, 1));
        mx0 = fmaxf(mx0, __shfl_xor_sync(0xffffffffu, mx0, 2));
        mx1 = fmaxf(mx1, __shfl_xor_sync(0xffffffffu, mx1, 1));
        mx1 = fmaxf(mx1, __shfl_xor_sync(0xffffffffu, mx1, 2));

        float mn0 = fmaxf(m0, mx0), mn1 = fmaxf(m1, mx1);
        float sc0 = fexp2((m0 - mn0) * L2E), sc1 = fexp2((m1 - mn1) * L2E);
        float b0 = mn0 * L2E, b1 = mn1 * L2E;
        float lp0 = 0.f, lp1 = 0.f;
#pragma unroll
        for (int nb = 0; nb < 8; nb++) {
            float p0 = fexp2(fmaf(Sa[nb][0], L2E, -b0));
            float p1 = fexp2(fmaf(Sa[nb][1], L2E, -b0));
            float p2 = fexp2(fmaf(Sa[nb][2], L2E, -b1));
            float p3 = fexp2(fmaf(Sa[nb][3], L2E, -b1));
            Sa[nb][0] = p0; Sa[nb][1] = p1; Sa[nb][2] = p2; Sa[nb][3] = p3;
            lp0 += p0 + p1; lp1 += p2 + p3;
        }
        l0 = l0 * sc0 + lp0;
        l1 = l1 * sc1 + lp1;
#pragma unroll
        for (int nb = 0; nb < 16; nb++) {
            O[nb][0] *= sc0; O[nb][1] *= sc0;
            O[nb][2] *= sc1; O[nb][3] *= sc1;
        }
        m0 = mn0; m1 = mn1;

        // ---- O += P . V (3-term split) ----
#pragma unroll
        for (int ks = 0; ks < 4; ks++) {
            uint32_t pah[4], pal[4];
#pragma unroll
            for (int u = 0; u < 4; u++) {
                const float* src = Sa[2 * ks + (u >> 1)];
                float x0 = src[(u & 1) * 2], x1 = src[(u & 1) * 2 + 1];
                __nv_bfloat16 h0 = __float2bfloat16_rn(x0);
                __nv_bfloat16 h1 = __float2bfloat16_rn(x1);
                __nv_bfloat162 hp; hp.x = h0; hp.y = h1;
                pah[u] = *reinterpret_cast<uint32_t*>(&hp);
                pal[u] = pack2(x0 - __bfloat162float(h0), x1 - __bfloat162float(h1));
            }
#pragma unroll
            for (int grp = 0; grp < 2; grp++) {
                uint32_t vh[4][4], vl[4][4];
#pragma unroll
                for (int j = 0; j < 4; j++) {
                    int np = grp * 4 + j;
                    ldsm4t(vh[j], sb + SV_H + vbase + ks * 4352 + np * 32);
                    ldsm4t(vl[j], sb + SV_L + vbase + ks * 4352 + np * 32);
                }
#pragma unroll
                for (int j = 0; j < 4; j++) {
                    int np = grp * 4 + j;
                    mma16816(O[np * 2],     pah, vh[j][0], vh[j][2]);
                    mma16816(O[np * 2 + 1], pah, vh[j][1], vh[j][3]);
                }
#pragma unroll
                for (int j = 0; j < 4; j++) {
                    int np = grp * 4 + j;
                    mma16816(O[np * 2],     pal, vh[j][0], vh[j][2]);
                    mma16816(O[np * 2 + 1], pal, vh[j][1], vh[j][3]);
                }
#pragma unroll
                for (int j = 0; j < 4; j++) {
                    int np = grp * 4 + j;
                    mma16816(O[np * 2],     pah, vl[j][0], vl[j][2]);
                    mma16816(O[np * 2 + 1], pah, vl[j][1], vl[j][3]);
                }
            }
        }
    }

    // ---- epilogue: normalize + head-sum via atomics ----
    l0 += __shfl_xor_sync(0xffffffffu, l0, 1);
    l0 += __shfl_xor_sync(0xffffffffu, l0, 2);
    l1 += __shfl_xor_sync(0xffffffffu, l1, 1);
    l1 += __shfl_xor_sync(0xffffffffu, l1, 2);
    float inv0 = 1.0f / l0, inv1 = 1.0f / l1;
    int r0 = i0 + wid * 16 + (lane >> 2), r1 = r0 + 8;
    int cb = (lane & 3) * 2;
#pragma unroll
    for (int nb = 0; nb < 16; nb++) {
        int col = nb * 8 + cb;
        atomicAdd(&out[r0 * ND + col],     O[nb][0] * inv0);
        atomicAdd(&out[r0 * ND + col + 1], O[nb][1] * inv0);
        atomicAdd(&out[r1 * ND + col],     O[nb][2] * inv1);
        atomicAdd(&out[r1 * ND + col + 1], O[nb][3] * inv1);
    }
}

// ---------------------------------------------------------------------------
extern "C" void kernel_launch(void* const* d_in, const int* in_sizes, int n_in,
                              void* d_out, int out_size) {
    const float* nodes = (const float*)d_in[0];
    const float* pos   = (const float*)d_in[1];
    const float* rotv  = (const float*)d_in[2];
    const float* wN    = (const float*)d_in[3];
    const float* bN    = (const float*)d_in[4];
    const float* wP    = (const float*)d_in[5];
    const float* bP    = (const float*)d_in[6];
    const float* wR    = (const float*)d_in[7];
    const float* wV    = (const float*)d_in[8];
    const float* bV    = (const float*)d_in[9];
    float* out = (float*)d_out;

    zero_kernel<<<(S * ND + 255) / 256, 256>>>(out);

    cudaFuncSetAttribute(val_kernel, cudaFuncAttributeMaxDynamicSharedMemorySize, VAL_SMEM);
    val_kernel<<<dim3(3072 / 64, S / 64), 256, VAL_SMEM>>>(nodes, wV, bV);

    kq_kernel<<<dim3(512 / 32, S / 32), 256>>>(nodes, pos, rotv, wN, bN, wP, bP, wR);

    cudaFuncSetAttribute(attn_mma, cudaFuncAttributeMaxDynamicSharedMemorySize, SMEM_B);
    attn_mma<<<dim3(S / 64, NH), 128, SMEM_B>>>(out);
}